// round 7
// baseline (speedup 1.0000x reference)
#include <cuda_runtime.h>
#include <math.h>

#define K        8
#define C4       64          // 16-byte columns per row (d=256 floats)
#define TILE_N   64          // output rows per block
#define RPT      32          // rows per thread
#define THREADS  128         // 64 cols x 2 groups
#define WIN      20          // register pipeline depth (window 8 + prefetch 12)
#define NEGV     (-1e9f)

typedef unsigned long long u64;

// packed fp32x2 FMA (FFMA2 path, only reachable via PTX)
__device__ __forceinline__ void fma2(u64& acc, u64 v, u64 a) {
    asm("fma.rn.f32x2 %0, %1, %2, %3;" : "=l"(acc) : "l"(v), "l"(a), "l"(acc));
}
__device__ __forceinline__ u64 pack2(float a) {
    u64 d;
    asm("mov.b64 %0, {%1, %1};" : "=l"(d) : "f"(a));
    return d;
}

// valid_mask may arrive as int32 / uint8(bool) / float32; detect from word 0
// (guaranteed "true" since lengths >= N/2).
__device__ __forceinline__ bool mask_at(const void* m, int fmt, long i) {
    if (fmt == 1) return ((const unsigned char*)m)[i] != 0;
    if (fmt == 2) return ((const float*)m)[i] != 0.0f;
    return ((const int*)m)[i] != 0;
}

__global__ __launch_bounds__(THREADS)
void mixer_kernel(const float* __restrict__ x,
                  const float* __restrict__ dts,
                  const void*  __restrict__ maskp,
                  const float* __restrict__ w,
                  const float* __restrict__ beta,
                  float* __restrict__ out,
                  int N)
{
    // alphas pre-duplicated as {a,a} u64 -> inner loop needs no packing MOVs
    __shared__ u64 s_alpha2[TILE_N * K];

    const int  b    = blockIdx.y;
    const int  n0   = blockIdx.x * TILE_N;
    const int  tid  = threadIdx.x;
    const long base = (long)b * N;

    // ---- per-thread column/row-strip mapping (phase 2) ----
    const int c4     = tid & (C4 - 1);   // 0..63
    const int g      = tid >> 6;         // 0..1
    const int r0     = g * RPT;
    const int nstart = n0 + r0;

    const ulonglong2* __restrict__ xr =
        (const ulonglong2*)x + (base + nstart) * (long)C4 + c4;
    ulonglong2* __restrict__ orow =
        (ulonglong2*)out + (base + nstart) * (long)C4 + c4;

    // ---- issue pipeline-init loads FIRST (20 independent LDG.128) ----
    ulonglong2 buf[WIN];
    #pragma unroll
    for (int j = 0; j < WIN; j++) {
        const int nr = nstart + j;
        buf[j] = (nr < N) ? xr[(long)j * C4] : make_ulonglong2(0ULL, 0ULL);
    }

    // ---- mask format detection (uniform) ----
    const unsigned int w0 = *((const unsigned int*)maskp);
    int fmt = 0;
    if (w0 == 0x01010101u)      fmt = 1;   // uint8 bool
    else if (w0 == 0x3F800000u) fmt = 2;   // float32

    // ================= Phase 1: alpha[TILE_N][K] (overlaps window loads) ====
    if (tid < TILE_N) {
        const int  n      = n0 + tid;
        const bool valid0 = mask_at(maskp, fmt, base + n);
        const float dt0   = dts[base + n];

        float score[K];
        bool  cv[K];
        cv[0]    = valid0;
        score[0] = valid0 ? 0.0f : NEGV;
        #pragma unroll
        for (int p = 1; p < K; p++) {
            const int np = n + p;
            bool  c  = false;
            float td = 0.0f;
            if (np < N) {
                c = valid0 && mask_at(maskp, fmt, base + np);
                if (c) td = fmaxf(dts[base + np] - dt0, 0.0f);
            }
            cv[p]    = c;
            score[p] = c ? -td : NEGV;
        }

        float m = score[0];
        #pragma unroll
        for (int p = 1; p < K; p++) m = fmaxf(m, score[p]);
        float e[K], es = 0.0f;
        #pragma unroll
        for (int p = 0; p < K; p++) { e[p] = __expf(score[p] - m); es += e[p]; }
        const float inv_es = 1.0f / es;

        float wv[K];
        #pragma unroll
        for (int p = 0; p < K; p++) wv[p] = w[p];
        float wm = wv[0];
        #pragma unroll
        for (int p = 1; p < K; p++) wm = fmaxf(wm, wv[p]);
        float we[K], ws = 0.0f;
        #pragma unroll
        for (int p = 0; p < K; p++) { we[p] = __expf(wv[p] - wm); ws += we[p]; }
        const float inv_ws = 1.0f / ws;
        const float bsig   = 1.0f / (1.0f + __expf(-beta[0]));
        const float omb    = 1.0f - bsig;

        float a[K], asum = 0.0f;
        #pragma unroll
        for (int p = 0; p < K; p++) {
            a[p] = cv[p] ? (bsig * we[p] * inv_ws + omb * e[p] * inv_es) : 0.0f;
            asum += a[p];
        }
        const float inv = 1.0f / fmaxf(asum, 1e-8f);
        #pragma unroll
        for (int p = 0; p < K; p++) s_alpha2[tid * K + p] = pack2(a[p] * inv);
    }
    __syncthreads();

    // ========== Phase 2: pipelined sliding window, 1 LDG per output ========
    // Fully unrolled; ring indices compile-time. Prefetch for row r+WIN is
    // ISSUED before the FMAs (temp) and COMMITTED to buf[r%WIN] after row r
    // is consumed. Steady-state load-to-use distance = WIN-K+1 = 13.
    #pragma unroll
    for (int r = 0; r < RPT; r++) {
        ulonglong2 nv;
        if (r < RPT - 1) {
            const int nr = nstart + r + WIN;
            nv = (nr < N) ? xr[(long)(r + WIN) * C4] : make_ulonglong2(0ULL, 0ULL);
        }

        // 8 pre-packed alphas: 4x LDS.128 broadcast
        const ulonglong2* ar = (const ulonglong2*)&s_alpha2[(r0 + r) * K];
        const ulonglong2 q0 = ar[0], q1 = ar[1], q2 = ar[2], q3 = ar[3];
        const u64 ap[K] = {q0.x, q0.y, q1.x, q1.y, q2.x, q2.y, q3.x, q3.y};

        u64 accx = 0ULL, accy = 0ULL;
        #pragma unroll
        for (int p = 0; p < K; p++) {
            const ulonglong2 v = buf[(r + p) % WIN];
            fma2(accx, v.x, ap[p]);
            fma2(accy, v.y, ap[p]);
        }
        orow[(long)r * C4] = make_ulonglong2(accx, accy);

        if (r < RPT - 1) {
            buf[r % WIN] = nv;   // row r consumed above; safe to recycle slot
        }
    }
}

extern "C" void kernel_launch(void* const* d_in, const int* in_sizes, int n_in,
                              void* d_out, int out_size)
{
    const float* x    = (const float*)d_in[0];
    const float* dts  = (const float*)d_in[1];
    const void*  mask = d_in[2];
    const float* w    = (const float*)d_in[3];
    const float* beta = (const float*)d_in[4];

    const int BN = in_sizes[1];   // B * N
    const int B  = 8;
    const int N  = BN / B;        // 4096

    dim3 grid(N / TILE_N, B);
    mixer_kernel<<<grid, THREADS>>>(x, dts, mask, w, beta, (float*)d_out, N);
}

// round 8
// speedup vs baseline: 1.0878x; 1.0878x over previous
#include <cuda_runtime.h>
#include <math.h>

#define K        8
#define C4       64          // 16-byte columns per row (d=256 floats)
#define TILE_N   64          // output rows per block
#define RPT      32          // rows per thread
#define THREADS  128         // 64 cols x 2 groups
#define WIN      16          // register pipeline depth (window 8 + prefetch 8)
#define NEGV     (-1e9f)

typedef unsigned long long u64;

// packed fp32x2 FMA (FFMA2 path, only reachable via PTX)
__device__ __forceinline__ void fma2(u64& acc, u64 v, u64 a) {
    asm("fma.rn.f32x2 %0, %1, %2, %3;" : "=l"(acc) : "l"(v), "l"(a), "l"(acc));
}
__device__ __forceinline__ u64 pack2(float a) {
    u64 d;
    asm("mov.b64 %0, {%1, %1};" : "=l"(d) : "f"(a));
    return d;
}

// valid_mask may arrive as int32 / uint8(bool) / float32; detect from word 0
// (guaranteed "true" since lengths >= N/2).
__device__ __forceinline__ bool mask_at(const void* m, int fmt, long i) {
    if (fmt == 1) return ((const unsigned char*)m)[i] != 0;
    if (fmt == 2) return ((const float*)m)[i] != 0.0f;
    return ((const int*)m)[i] != 0;
}

__global__ __launch_bounds__(THREADS)
void mixer_kernel(const float* __restrict__ x,
                  const float* __restrict__ dts,
                  const void*  __restrict__ maskp,
                  const float* __restrict__ w,
                  const float* __restrict__ beta,
                  float* __restrict__ out,
                  int N)
{
    // alphas pre-duplicated as {a,a} u64 -> inner loop needs no packing MOVs
    __shared__ u64 s_alpha2[TILE_N * K];

    const int  b    = blockIdx.y;
    const int  n0   = blockIdx.x * TILE_N;
    const int  tid  = threadIdx.x;
    const long base = (long)b * N;

    // ---- per-thread column/row-strip mapping (phase 2) ----
    const int c4     = tid & (C4 - 1);   // 0..63
    const int g      = tid >> 6;         // 0..1
    const int r0     = g * RPT;
    const int nstart = n0 + r0;

    const ulonglong2* __restrict__ xr =
        (const ulonglong2*)x + (base + nstart) * (long)C4 + c4;
    ulonglong2* __restrict__ orow =
        (ulonglong2*)out + (base + nstart) * (long)C4 + c4;

    // ---- issue pipeline-init loads FIRST (16 independent LDG.128) ----
    ulonglong2 buf[WIN];
    #pragma unroll
    for (int j = 0; j < WIN; j++) {
        const int nr = nstart + j;
        buf[j] = (nr < N) ? xr[(long)j * C4] : make_ulonglong2(0ULL, 0ULL);
    }

    // ---- mask format detection (uniform) ----
    const unsigned int w0 = *((const unsigned int*)maskp);
    int fmt = 0;
    if (w0 == 0x01010101u)      fmt = 1;   // uint8 bool
    else if (w0 == 0x3F800000u) fmt = 2;   // float32

    // ================= Phase 1: alpha[TILE_N][K] (overlaps window loads) ====
    if (tid < TILE_N) {
        const int  n      = n0 + tid;
        const bool valid0 = mask_at(maskp, fmt, base + n);
        const float dt0   = dts[base + n];

        float score[K];
        bool  cv[K];
        cv[0]    = valid0;
        score[0] = valid0 ? 0.0f : NEGV;
        #pragma unroll
        for (int p = 1; p < K; p++) {
            const int np = n + p;
            bool  c  = false;
            float td = 0.0f;
            if (np < N) {
                c = valid0 && mask_at(maskp, fmt, base + np);
                if (c) td = fmaxf(dts[base + np] - dt0, 0.0f);
            }
            cv[p]    = c;
            score[p] = c ? -td : NEGV;
        }

        float m = score[0];
        #pragma unroll
        for (int p = 1; p < K; p++) m = fmaxf(m, score[p]);
        float e[K], es = 0.0f;
        #pragma unroll
        for (int p = 0; p < K; p++) { e[p] = __expf(score[p] - m); es += e[p]; }
        const float inv_es = 1.0f / es;

        float wv[K];
        #pragma unroll
        for (int p = 0; p < K; p++) wv[p] = w[p];
        float wm = wv[0];
        #pragma unroll
        for (int p = 1; p < K; p++) wm = fmaxf(wm, wv[p]);
        float we[K], ws = 0.0f;
        #pragma unroll
        for (int p = 0; p < K; p++) { we[p] = __expf(wv[p] - wm); ws += we[p]; }
        const float inv_ws = 1.0f / ws;
        const float bsig   = 1.0f / (1.0f + __expf(-beta[0]));
        const float omb    = 1.0f - bsig;

        float a[K], asum = 0.0f;
        #pragma unroll
        for (int p = 0; p < K; p++) {
            a[p] = cv[p] ? (bsig * we[p] * inv_ws + omb * e[p] * inv_es) : 0.0f;
            asum += a[p];
        }
        const float inv = 1.0f / fmaxf(asum, 1e-8f);
        #pragma unroll
        for (int p = 0; p < K; p++) s_alpha2[tid * K + p] = pack2(a[p] * inv);
    }
    __syncthreads();

    // ========== Phase 2: pipelined sliding window (R4 pattern) =============
    // Consume slot r%WIN first, THEN load row r+WIN directly into that slot.
    // No temp, no completion wait: the LDG's first consumer is 9 iterations
    // later. Dead prefetches (rows beyond the last tap RPT-1+7) are skipped
    // at compile time: load row r+WIN only if r+WIN <= RPT+K-2.
    #pragma unroll
    for (int r = 0; r < RPT; r++) {
        // 8 pre-packed alphas: 4x LDS.128 broadcast, no MOVs
        const ulonglong2* ar = (const ulonglong2*)&s_alpha2[(r0 + r) * K];
        const ulonglong2 q0 = ar[0], q1 = ar[1], q2 = ar[2], q3 = ar[3];
        const u64 ap[K] = {q0.x, q0.y, q1.x, q1.y, q2.x, q2.y, q3.x, q3.y};

        u64 accx = 0ULL, accy = 0ULL;
        #pragma unroll
        for (int p = 0; p < K; p++) {
            const ulonglong2 v = buf[(r + p) & (WIN - 1)];
            fma2(accx, v.x, ap[p]);
            fma2(accy, v.y, ap[p]);
        }
        orow[(long)r * C4] = make_ulonglong2(accx, accy);

        if (r + WIN <= RPT + K - 2) {     // compile-time: only useful rows
            const int nr = nstart + r + WIN;
            buf[r & (WIN - 1)] =
                (nr < N) ? xr[(long)(r + WIN) * C4] : make_ulonglong2(0ULL, 0ULL);
        }
    }
}

extern "C" void kernel_launch(void* const* d_in, const int* in_sizes, int n_in,
                              void* d_out, int out_size)
{
    const float* x    = (const float*)d_in[0];
    const float* dts  = (const float*)d_in[1];
    const void*  mask = d_in[2];
    const float* w    = (const float*)d_in[3];
    const float* beta = (const float*)d_in[4];

    const int BN = in_sizes[1];   // B * N
    const int B  = 8;
    const int N  = BN / B;        // 4096

    dim3 grid(N / TILE_N, B);
    mixer_kernel<<<grid, THREADS>>>(x, dts, mask, w, beta, (float*)d_out, N);
}

// round 9
// speedup vs baseline: 1.1572x; 1.0639x over previous
#include <cuda_runtime.h>
#include <math.h>

#define K        8
#define C4       64          // 16-byte columns per row (d=256 floats)
#define TILE_N   64          // output rows per block
#define RPT      32          // rows per thread
#define THREADS  128         // 64 cols x 2 groups
#define BATCH    8           // rows per load/compute batch
#define NBATCH   (RPT / BATCH)   // 4 output batches
#define RING     24          // 3 batches of 8 rows resident
#define MAXROW   (RPT + K - 2)   // last row ever tapped (38)
#define NEGV     (-1e9f)

typedef unsigned long long u64;

// packed fp32x2 FMA (FFMA2 path, only reachable via PTX)
__device__ __forceinline__ void fma2(u64& acc, u64 v, u64 a) {
    asm("fma.rn.f32x2 %0, %1, %2, %3;" : "=l"(acc) : "l"(v), "l"(a), "l"(acc));
}
__device__ __forceinline__ u64 pack2(float a) {
    u64 d;
    asm("mov.b64 %0, {%1, %1};" : "=l"(d) : "f"(a));
    return d;
}

// valid_mask may arrive as int32 / uint8(bool) / float32; detect from word 0
// (guaranteed "true" since lengths >= N/2).
__device__ __forceinline__ bool mask_at(const void* m, int fmt, long i) {
    if (fmt == 1) return ((const unsigned char*)m)[i] != 0;
    if (fmt == 2) return ((const float*)m)[i] != 0.0f;
    return ((const int*)m)[i] != 0;
}

__global__ __launch_bounds__(THREADS)
void mixer_kernel(const float* __restrict__ x,
                  const float* __restrict__ dts,
                  const void*  __restrict__ maskp,
                  const float* __restrict__ w,
                  const float* __restrict__ beta,
                  float* __restrict__ out,
                  int N)
{
    // alphas pre-duplicated as {a,a} u64 -> inner loop needs no packing MOVs
    __shared__ u64 s_alpha2[TILE_N * K];

    const int  b    = blockIdx.y;
    const int  n0   = blockIdx.x * TILE_N;
    const int  tid  = threadIdx.x;
    const long base = (long)b * N;

    // ---- per-thread column/row-strip mapping (phase 2) ----
    const int c4     = tid & (C4 - 1);   // 0..63
    const int g      = tid >> 6;         // 0..1
    const int r0     = g * RPT;
    const int nstart = n0 + r0;

    const ulonglong2* __restrict__ xr =
        (const ulonglong2*)x + (base + nstart) * (long)C4 + c4;
    ulonglong2* __restrict__ orow =
        (ulonglong2*)out + (base + nstart) * (long)C4 + c4;

    // ---- batched pipeline init: row-batches 0 and 1 (16 LDG.128) ----
    ulonglong2 buf[RING];
    #pragma unroll
    for (int j = 0; j < 2 * BATCH; j++) {
        const int nr = nstart + j;
        buf[j] = (nr < N) ? xr[(long)j * C4] : make_ulonglong2(0ULL, 0ULL);
    }

    // ---- mask format detection (uniform) ----
    const unsigned int w0 = *((const unsigned int*)maskp);
    int fmt = 0;
    if (w0 == 0x01010101u)      fmt = 1;   // uint8 bool
    else if (w0 == 0x3F800000u) fmt = 2;   // float32

    // ================= Phase 1: alpha[TILE_N][K] (overlaps batch loads) ====
    if (tid < TILE_N) {
        const int  n      = n0 + tid;
        const bool valid0 = mask_at(maskp, fmt, base + n);
        const float dt0   = dts[base + n];

        float score[K];
        bool  cv[K];
        cv[0]    = valid0;
        score[0] = valid0 ? 0.0f : NEGV;
        #pragma unroll
        for (int p = 1; p < K; p++) {
            const int np = n + p;
            bool  c  = false;
            float td = 0.0f;
            if (np < N) {
                c = valid0 && mask_at(maskp, fmt, base + np);
                if (c) td = fmaxf(dts[base + np] - dt0, 0.0f);
            }
            cv[p]    = c;
            score[p] = c ? -td : NEGV;
        }

        float m = score[0];
        #pragma unroll
        for (int p = 1; p < K; p++) m = fmaxf(m, score[p]);
        float e[K], es = 0.0f;
        #pragma unroll
        for (int p = 0; p < K; p++) { e[p] = __expf(score[p] - m); es += e[p]; }
        const float inv_es = 1.0f / es;

        float wv[K];
        #pragma unroll
        for (int p = 0; p < K; p++) wv[p] = w[p];
        float wm = wv[0];
        #pragma unroll
        for (int p = 1; p < K; p++) wm = fmaxf(wm, wv[p]);
        float we[K], ws = 0.0f;
        #pragma unroll
        for (int p = 0; p < K; p++) { we[p] = __expf(wv[p] - wm); ws += we[p]; }
        const float inv_ws = 1.0f / ws;
        const float bsig   = 1.0f / (1.0f + __expf(-beta[0]));
        const float omb    = 1.0f - bsig;

        float a[K], asum = 0.0f;
        #pragma unroll
        for (int p = 0; p < K; p++) {
            a[p] = cv[p] ? (bsig * we[p] * inv_ws + omb * e[p] * inv_es) : 0.0f;
            asum += a[p];
        }
        const float inv = 1.0f / fmaxf(asum, 1e-8f);
        #pragma unroll
        for (int p = 0; p < K; p++) s_alpha2[tid * K + p] = pack2(a[p] * inv);
    }
    __syncthreads();

    // ========== Phase 2: batch-pipelined sliding window =====================
    // Ring of 24 rows = 3 batches of 8. Steady state per output-batch bb:
    //   1) issue the 8 loads of row-batch bb+2 back-to-back (they share wbar
    //      slots only among themselves),
    //   2) compute outputs 8*bb..8*bb+7 from row-batches bb, bb+1 (loaded a
    //      full compute-phase earlier -> their scoreboard wait is long drained
    //      and does NOT alias with the in-flight batch).
    #pragma unroll
    for (int bb = 0; bb < NBATCH; bb++) {
        // ---- 1) load row-batch bb+2 ----
        if (bb + 2 <= NBATCH) {                    // compile-time
            #pragma unroll
            for (int j = 0; j < BATCH; j++) {
                const int row = (bb + 2) * BATCH + j;
                if (row <= MAXROW) {               // skip never-tapped rows
                    const int nr = nstart + row;
                    buf[row % RING] =
                        (nr < N) ? xr[(long)row * C4] : make_ulonglong2(0ULL, 0ULL);
                }
            }
        }

        // ---- 2) compute outputs of batch bb ----
        #pragma unroll
        for (int r = 0; r < BATCH; r++) {
            const int o = bb * BATCH + r;          // local output row

            // 8 pre-packed alphas: 4x LDS.128 broadcast
            const ulonglong2* ar = (const ulonglong2*)&s_alpha2[(r0 + o) * K];
            const ulonglong2 q0 = ar[0], q1 = ar[1], q2 = ar[2], q3 = ar[3];
            const u64 ap[K] = {q0.x, q0.y, q1.x, q1.y, q2.x, q2.y, q3.x, q3.y};

            u64 accx = 0ULL, accy = 0ULL;
            #pragma unroll
            for (int p = 0; p < K; p++) {
                const ulonglong2 v = buf[(o + p) % RING];
                fma2(accx, v.x, ap[p]);
                fma2(accy, v.y, ap[p]);
            }
            orow[(long)o * C4] = make_ulonglong2(accx, accy);
        }
    }
}

extern "C" void kernel_launch(void* const* d_in, const int* in_sizes, int n_in,
                              void* d_out, int out_size)
{
    const float* x    = (const float*)d_in[0];
    const float* dts  = (const float*)d_in[1];
    const void*  mask = d_in[2];
    const float* w    = (const float*)d_in[3];
    const float* beta = (const float*)d_in[4];

    const int BN = in_sizes[1];   // B * N
    const int B  = 8;
    const int N  = BN / B;        // 4096

    dim3 grid(N / TILE_N, B);
    mixer_kernel<<<grid, THREADS>>>(x, dts, mask, w, beta, (float*)d_out, N);
}